// round 17
// baseline (speedup 1.0000x reference)
#include <cuda_runtime.h>
#include <cuda_fp16.h>
#include <cstdint>

#define H       64
#define K       256
#define TILE_M  64
#define TPB     256
#define MARGIN  1.5f
#define BFS     144                      // f16 row stride in bytes
#define FLT_INF 3.402823466e+38f
#define QMAXG   512                      // queue entries per group

// ---- dynamic smem layout (bytes) ----
#define OFF_CBF   0                      // B = f16(c): 256*144 = 36864
#define OFF_XBF   36864                  // X f16(-2x): 64*144 = 9216 -> 46080
#define OFF_C2    46080                  // ||c||^2 fp32 exact (pad 1024) -> 47104
#define OFF_C2P   47104                  // c2 packed f16x2: 128*4 -> 47616
#define OFF_RMIN  47616                  // 64 rows * 4 quarters * 4B -> 48640
#define OFF_CNT   48640                  // cnt per (row, quarter): 64*4*4 -> 49664
#define OFF_K1    49664                  // single-k per (row, quarter): 64*4*4 -> 50688
#define OFF_RES   50688                  // packed (d2,k) per row: 64*8 -> 51200
#define OFF_Q     51200                  // 2 groups * 512 * 4 -> 55296
#define OFF_QN    55296                  // 2 counters, 32B apart -> 55360
#define OFF_OFL   55360                  // 64*4 -> 55616
#define SMEM_TOTAL 55616

#define GBAR(g) asm volatile("bar.sync %0, 128;" :: "r"((g) + 1) : "memory")

__device__ __forceinline__ uint32_t smem_u32(const void* p) {
    uint32_t a;
    asm("{ .reg .u64 t; cvta.to.shared.u64 t, %1; cvt.u32.u64 %0, t; }" : "=r"(a) : "l"(p));
    return a;
}

__device__ __forceinline__ uint32_t f16x2_pack(float lo, float hi) {
    __half2 h = __floats2half2_rn(lo, hi);
    return *(uint32_t*)&h;
}

__device__ __forceinline__ void ldsm4(uint32_t* r, uint32_t addr) {
    asm volatile("ldmatrix.sync.aligned.m8n8.x4.shared.b16 {%0,%1,%2,%3}, [%4];"
        : "=r"(r[0]), "=r"(r[1]), "=r"(r[2]), "=r"(r[3]) : "r"(addr));
}

// f16 in, f16 acc: d0 = row g cols{k0,k0+1}, d1 = row g+8 same cols
__device__ __forceinline__ void mma_f16(uint32_t& d0, uint32_t& d1,
                                        const uint32_t* a, const uint32_t* b) {
    asm volatile("mma.sync.aligned.m16n8k16.row.col.f16.f16.f16.f16 "
        "{%0,%1}, {%2,%3,%4,%5}, {%6,%7}, {%0,%1};"
        : "+r"(d0), "+r"(d1)
        : "r"(a[0]), "r"(a[1]), "r"(a[2]), "r"(a[3]), "r"(b[0]), "r"(b[1]));
}

// exact rescore (sequential-h fp32, float4 loads from gmem), monotone-packed (d2,k)
__device__ __forceinline__ unsigned long long rescore_pack(const float* __restrict__ xr,
                                                           const float* __restrict__ crow,
                                                           float c2k, int k) {
    float x2 = 0.f, dot = 0.f;
    #pragma unroll
    for (int h4 = 0; h4 < H / 4; ++h4) {
        float4 xv = __ldg((const float4*)(xr + h4 * 4));
        float4 cv = __ldg((const float4*)(crow + h4 * 4));
        x2 = __fadd_rn(x2, __fmul_rn(xv.x, xv.x));
        dot = __fmaf_rn(xv.x, cv.x, dot);
        x2 = __fadd_rn(x2, __fmul_rn(xv.y, xv.y));
        dot = __fmaf_rn(xv.y, cv.y, dot);
        x2 = __fadd_rn(x2, __fmul_rn(xv.z, xv.z));
        dot = __fmaf_rn(xv.z, cv.z, dot);
        x2 = __fadd_rn(x2, __fmul_rn(xv.w, xv.w));
        dot = __fmaf_rn(xv.w, cv.w, dot);
    }
    float d2 = __fmaf_rn(-2.f, dot, __fadd_rn(x2, c2k));
    uint32_t b = __float_as_uint(d2);
    b ^= (b & 0x80000000u) ? 0xFFFFFFFFu : 0x80000000u;    // monotone map
    return ((unsigned long long)b << 32) | (unsigned)k;
}

extern __shared__ char smem_raw[];

__global__ __launch_bounds__(TPB, 3)
void LatentSpaceClustering_46797963657837_kernel(const float* __restrict__ x,
                                                 const float* __restrict__ c,
                                                 float* __restrict__ out,
                                                 int n, int num_tiles) {
    const uint32_t sbase = smem_u32(smem_raw);
    float*    c2f  = (float*)(smem_raw + OFF_C2);
    uint32_t* c2p  = (uint32_t*)(smem_raw + OFF_C2P);
    float*    rmin = (float*)(smem_raw + OFF_RMIN);
    int*      cntq = (int*)(smem_raw + OFF_CNT);
    int*      k1q  = (int*)(smem_raw + OFF_K1);
    unsigned long long* res = (unsigned long long*)(smem_raw + OFF_RES);
    int* ofl = (int*)(smem_raw + OFF_OFL);
    const int tid = threadIdx.x;
    const int lane = tid & 31, w = tid >> 5;
    const int groupID = lane >> 2, tig = lane & 3;
    const int q4 = w & 3, g = w >> 2;               // n-quarter, m-group
    const int gtid = tid & 127;                     // 0..127 within group
    const int nb = q4 * 64;                         // n base for this warp

    uint32_t* qg  = (uint32_t*)(smem_raw + OFF_Q) + g * QMAXG;
    int*      qnp = (int*)(smem_raw + OFF_QN + g * 32);

    // ---- stage B = f16(-2c) (padded rows) ----
    {
        const float4* c4 = (const float4*)c;
        for (int j = tid; j < K * H / 4; j += TPB) {
            float4 v = c4[j];
            int k = j >> 4, h = (j & 15) << 2;
            uint2 p = make_uint2(f16x2_pack(-2.f * v.x, -2.f * v.y),
                                 f16x2_pack(-2.f * v.z, -2.f * v.w));
            *(uint2*)(smem_raw + OFF_CBF + k * BFS + h * 2) = p;
        }
    }
    // ---- exact ||c_k||^2 (fp32 sequential, reference-style) ----
    {
        int k = tid;                                // TPB == K
        const float* cr = c + k * H;
        float s = 0.f;
        #pragma unroll 8
        for (int h = 0; h < H; ++h) {
            float v = __ldg(cr + h);
            s = __fadd_rn(s, __fmul_rn(v, v));
        }
        c2f[k] = s;
    }
    __syncthreads();
    if (tid < 128) c2p[tid] = f16x2_pack(c2f[2 * tid], c2f[2 * tid + 1]);
    __syncthreads();

    const uint32_t a_base = sbase + OFF_XBF + (g * 32 + (lane & 15)) * BFS + ((lane >> 4) * 16);
    const uint32_t b_base = sbase + OFF_CBF
        + (nb + (lane & 7) + ((lane >> 4) << 3)) * BFS
        + (((lane >> 3) & 1) * 16);
    // 4 rows owned by this thread (local to group): groupID + {0,8,16,24}
    const int rl0 = groupID;

    for (int tile = blockIdx.x; tile < num_tiles; tile += gridDim.x) {
        const long long gbase = (long long)tile * TILE_M + g * 32;

        // ---- stage X f16 (group's 32 rows); reset queue counter ----
        #pragma unroll
        for (int i = 0; i < 4; ++i) {
            int chunk = i * 128 + gtid;             // 512 = 32 rows * 16 float4
            int row = chunk >> 4, h4 = chunk & 15;
            float4 v = make_float4(0.f, 0.f, 0.f, 0.f);
            if (gbase + row < n)
                v = __ldg((const float4*)(x + (gbase + row) * H + h4 * 4));
            uint2 p = make_uint2(f16x2_pack(v.x, v.y), f16x2_pack(v.z, v.w));
            *(uint2*)(smem_raw + OFF_XBF + (g * 32 + row) * BFS + h4 * 8) = p;
        }
        if (gtid == 0) *qnp = 0;
        GBAR(g);

        // ---- mma: acc(f16x2) init = c2; B = -2c => acc = c2 - 2 x.c ----
        uint32_t acc[4][8];                          // [row: g,g+8,g+16,g+24][ntile]
        #pragma unroll
        for (int nt = 0; nt < 8; ++nt) {
            uint32_t cv = c2p[nb / 2 + nt * 4 + tig];
            acc[0][nt] = cv; acc[1][nt] = cv; acc[2][nt] = cv; acc[3][nt] = cv;
        }
        uint32_t aa[2][4];                           // [mtile][regs]
        uint32_t bb[2][4];                           // double buffer over j2
        ldsm4(aa[0], a_base);
        ldsm4(aa[1], a_base + 16 * BFS);
        ldsm4(bb[0], b_base);
        #pragma unroll
        for (int ks = 0; ks < 4; ++ks) {
            #pragma unroll
            for (int j2 = 0; j2 < 4; ++j2) {
                int it = ks * 4 + j2, cur = it & 1;
                if (it < 15) {
                    int nx = it + 1;
                    ldsm4(bb[cur ^ 1], b_base + (nx & 3) * (16 * BFS) + (nx >> 2) * 32);
                }
                mma_f16(acc[0][j2 * 2],     acc[1][j2 * 2],     aa[0], bb[cur]);
                mma_f16(acc[0][j2 * 2 + 1], acc[1][j2 * 2 + 1], aa[0], bb[cur] + 2);
                mma_f16(acc[2][j2 * 2],     acc[3][j2 * 2],     aa[1], bb[cur]);
                mma_f16(acc[2][j2 * 2 + 1], acc[3][j2 * 2 + 1], aa[1], bb[cur] + 2);
                if (j2 == 3 && ks < 3) {             // after last use: reload A
                    ldsm4(aa[0], a_base + (ks + 1) * 32);
                    ldsm4(aa[1], a_base + 16 * BFS + (ks + 1) * 32);
                }
            }
        }

        // ---- per-row mins (packed), quad-reduce, publish ----
        float mn[4];
        #pragma unroll
        for (int r = 0; r < 4; ++r) {
            __half2 h = *(__half2*)&acc[r][0];
            #pragma unroll
            for (int nt = 1; nt < 8; ++nt) h = __hmin2(h, *(__half2*)&acc[r][nt]);
            float m = fminf(__low2float(h), __high2float(h));
            #pragma unroll
            for (int off = 1; off <= 2; off <<= 1)
                m = fminf(m, __shfl_xor_sync(0xffffffffu, m, off));
            mn[r] = m;
        }
        if (tig == 0) {
            #pragma unroll
            for (int r = 0; r < 4; ++r)
                rmin[(g * 32 + rl0 + r * 8) * 4 + q4] = mn[r];
        }
        GBAR(g);

        // ---- branch-free screen: 16-bit hit mask per row, counts via popc ----
        uint32_t msk[4];
        #pragma unroll
        for (int r = 0; r < 4; ++r) {
            int row = g * 32 + rl0 + r * 8;
            float4 mv = *(const float4*)(rmin + row * 4);
            float thr = fminf(fminf(mv.x, mv.y), fminf(mv.z, mv.w)) + MARGIN;
            __half2 t = __float2half2_rn(thr);
            uint32_t m = 0;
            #pragma unroll
            for (int nt = 0; nt < 8; ++nt) {
                __half2 cp = __hlt2(*(__half2*)&acc[r][nt], t);   // 1.0h per hit
                uint32_t u = *(uint32_t*)&cp;
                m |= (((u >> 10) & 1u) | ((u >> 25) & 2u)) << (nt * 2);
            }
            msk[r] = m;
            int cnt = __popc(m);
            int kk = -1;
            if (cnt == 1) {
                int b = __ffs(m) - 1;
                kk = nb + (b >> 1) * 8 + tig * 2 + (b & 1);
            }
            int cq = cnt, kq = kk;
            #pragma unroll
            for (int off = 1; off <= 2; off <<= 1) {
                cq += __shfl_xor_sync(0xffffffffu, cq, off);
                kq = max(kq, __shfl_xor_sync(0xffffffffu, kq, off));
            }
            if (tig == 0) { cntq[row * 4 + q4] = cq; k1q[row * 4 + q4] = kq; }
        }
        GBAR(g);

        // ---- resolve: singles direct; multis enqueue own mask bits ----
        #pragma unroll
        for (int r = 0; r < 4; ++r) {
            int row = g * 32 + rl0 + r * 8;
            int4 cv = *(const int4*)(cntq + row * 4);
            int total = cv.x + cv.y + cv.z + cv.w;
            if (q4 == 0 && tig == 0) {               // unique owner per row
                if (total == 1) {
                    int4 kv = *(const int4*)(k1q + row * 4);
                    res[row] = (unsigned)max(max(kv.x, kv.y), max(kv.z, kv.w));
                } else {
                    res[row] = 0xFFFFFFFFFFFFFFFFull;
                }
                ofl[row] = 0;
            }
            if (total > 1) {
                uint32_t m = msk[r];
                while (m) {
                    int b = __ffs(m) - 1; m &= m - 1;
                    int k = nb + (b >> 1) * 8 + tig * 2 + (b & 1);
                    int idx = atomicAdd(qnp, 1);
                    int rl = rl0 + r * 8;            // row local to group
                    if (idx < QMAXG) qg[idx] = ((uint32_t)rl << 8) | (uint32_t)k;
                    else ofl[row] = 1;
                }
            }
        }
        GBAR(g);

        // ---- group-parallel exact rescore ----
        {
            int total = *qnp;
            if (total > QMAXG) total = QMAXG;
            for (int i = gtid; i < total; i += 128) {
                uint32_t e = qg[i];
                int rl = e >> 8, k = e & 255;
                if (gbase + rl < n)
                    atomicMin(&res[g * 32 + rl],
                              rescore_pack(x + (size_t)(gbase + rl) * H,
                                           c + (size_t)k * H, c2f[k], k));
            }
        }
        // overflow fallback (pathological only)
        if (q4 == 0 && tig == 0) {
            #pragma unroll
            for (int r = 0; r < 4; ++r) {
                int row = g * 32 + rl0 + r * 8;
                int rl = rl0 + r * 8;
                if (ofl[row] && gbase + rl < n) {
                    for (int k = 0; k < K; ++k)
                        atomicMin(&res[row],
                                  rescore_pack(x + (size_t)(gbase + rl) * H,
                                               c + (size_t)k * H, c2f[k], k));
                }
            }
        }
        GBAR(g);

        // ---- write back (warp 0 of group: lane = local row) ----
        if (q4 == 0) {
            long long gp = gbase + lane;
            if (gp < n) out[gp] = (float)(uint32_t)(res[g * 32 + lane] & 0xFFFFFFFFull);
        }
    }
}

extern "C" void kernel_launch(void* const* d_in, const int* in_sizes, int n_in,
                              void* d_out, int out_size) {
    const float* x = (const float*)d_in[0];
    const float* c = (const float*)d_in[1];
    int n = in_sizes[0] / H;
    int num_tiles = (n + TILE_M - 1) / TILE_M;

    int sms = 148;
    cudaDeviceGetAttribute(&sms, cudaDevAttrMultiProcessorCount, 0);

    cudaFuncSetAttribute(LatentSpaceClustering_46797963657837_kernel,
                         cudaFuncAttributeMaxDynamicSharedMemorySize, SMEM_TOTAL);

    int grid = 3 * sms;
    if (grid > num_tiles) grid = num_tiles;
    LatentSpaceClustering_46797963657837_kernel<<<grid, TPB, SMEM_TOTAL>>>(
        x, c, (float*)d_out, n, num_tiles);
}